// round 13
// baseline (speedup 1.0000x reference)
#include <cuda_runtime.h>
#include <cuda_bf16.h>
#include <cstdint>

typedef unsigned long long ull;
typedef unsigned int uint;

#define N_BATCH 64
#define T_SEQ   2000
#define DQ      256
#define NTOK    10
#define NJ      80
#define NJT     10
#define TILE    64
#define N_ITEMS 2048         // 64 batches x 32 tiles
#define GRID_X  296          // 2 CTAs x 148 SMs, persistent-strided
#define THREADS 256
#define SCALE_LG 0.17677669529663687f
#define OUT_ELEMS (N_BATCH * T_SEQ * DQ)

// ---- smem (70,144 B/CTA -> 2 CTAs/SM, leaves ~91KB L1D) ----
#define XSTR   68            // uint2 per X row (544 B)
#define XBYTES 34816
#define OFF_X1 34816         // buf1; sLog/sAttn alias this (64 rows x 544 B)
#define OFF_IDX 69632        // 2 x 64 ints
#define SMEM_BYTES 70144
// sLog row = 8 head-slots x 64B + 32B pad. Slot h: logits fp32[10] then
// overwritten in-thread by packed attn bf16{hi,lo} uint2[8] (k-pairs, zero-padded).

__device__ uint4 g_Bf[NJT * 16 * 32];   // Wqk bf16 hi/lo, logits-MMA fragment order
__device__ uint4 g_Vf[8 * 4 * 32];      // vh bf16 hi/lo, V-MMA B-fragment order (16KB)
__device__ int   g_idx_is64;

// ---------- helpers ----------
__device__ __forceinline__ uint packbf(float x0, float x1) {
    uint r; asm("cvt.rn.bf16x2.f32 %0, %1, %2;" : "=r"(r) : "f"(x1), "f"(x0)); return r;
}
__device__ __forceinline__ float2 bf2f(uint u) {
    __nv_bfloat162 h = *reinterpret_cast<__nv_bfloat162*>(&u);
    return __bfloat1622float2(h);
}
__device__ __forceinline__ void mma16816(float* c,
    uint a0, uint a1, uint a2, uint a3, uint b0, uint b1) {
    asm volatile("mma.sync.aligned.m16n8k16.row.col.f32.bf16.bf16.f32 "
        "{%0,%1,%2,%3}, {%4,%5,%6,%7}, {%8,%9}, {%0,%1,%2,%3};"
        : "+f"(c[0]), "+f"(c[1]), "+f"(c[2]), "+f"(c[3])
        : "r"(a0), "r"(a1), "r"(a2), "r"(a3), "r"(b0), "r"(b1));
}

// =====================================================================
// Precompute: Wqk -> logits-fragment order; vh -> V-fragment order.
// =====================================================================
__global__ void precompute_kernel(const float* __restrict__ embed,
                                  const float* __restrict__ Wq,
                                  const float* __restrict__ Wk,
                                  const float* __restrict__ Wv,
                                  const int*   __restrict__ pidx) {
    __shared__ float skeys[NTOK * 32];
    const int tid = threadIdx.x;
    for (int e = tid; e < NTOK * 32; e += 256) skeys[e] = tanhf(embed[e]);
    __syncthreads();

    const int b = blockIdx.x;
    if (b < NJ) {
        const int h = b / NTOK, k = b % NTOK;
        __shared__ float skm[32];
        if (tid < 32) {
            float s = 0.f;
            #pragma unroll
            for (int d = 0; d < 32; ++d) s += skeys[k * 32 + d] * Wk[(h * 32 + tid) * 32 + d];
            skm[tid] = s;
        }
        __syncthreads();
        if (tid < 128) {
            const int c0 = 2 * tid;
            float s0 = 0.f, s1 = 0.f;
            #pragma unroll
            for (int d = 0; d < 32; ++d) {
                const float km = skm[d];
                s0 += km * Wq[(h * 32 + d) * DQ + c0];
                s1 += km * Wq[(h * 32 + d) * DQ + c0 + 1];
            }
            s0 *= SCALE_LG; s1 *= SCALE_LG;
            const uint hi = packbf(s0, s1);
            const float2 f = bf2f(hi);
            const uint lo = packbf(s0 - f.x, s1 - f.y);
            const int j = b >> 3, gr = b & 7;
            const int gk = tid >> 3, qq = tid & 7;
            const int q = qq & 3, hf = qq >> 2;
            uint* dst = (uint*)&g_Bf[(j * 16 + gk) * 32 + gr * 4 + q];
            dst[hf * 2]     = hi;
            dst[hf * 2 + 1] = lo;
        }
    } else {
        __shared__ float svh[NTOK * 256];
        for (int e = tid; e < NTOK * DQ; e += 256) {
            const int k = e >> 8, u = e & 255;
            float s = 0.f;
            #pragma unroll
            for (int d = 0; d < 32; ++d) s += skeys[k * 32 + d] * Wv[u * 32 + d];
            svh[k * 256 + u] = s;
        }
        __syncthreads();
        // V B-fragments: g_Vf[h*128 + j*32 + lane], lane=(gr*4+q):
        // b0 = vh[2q..2q+1][u], b1 = vh[2q+8..2q+9][u] (zero for k>=10), u=32h+8j+gr
        for (int e = tid; e < 1024; e += 256) {
            const int h = e >> 7, j = (e >> 5) & 3, lane = e & 31;
            const int gr = lane >> 2, q = lane & 3;
            const int u = 32 * h + 8 * j + gr;
            const float v0 = svh[(2 * q) * 256 + u];
            const float v1 = svh[(2 * q + 1) * 256 + u];
            const uint b0h = packbf(v0, v1);
            const float2 f0 = bf2f(b0h);
            const uint b0l = packbf(v0 - f0.x, v1 - f0.y);
            const float w0 = (q == 0) ? svh[8 * 256 + u] : 0.f;
            const float w1 = (q == 0) ? svh[9 * 256 + u] : 0.f;
            const uint b1h = packbf(w0, w1);
            const float2 f1 = bf2f(b1h);
            const uint b1l = packbf(w0 - f1.x, w1 - f1.y);
            g_Vf[e] = make_uint4(b0h, b0l, b1h, b1l);
        }
        if (tid == 0) {
            int is64 = 1;
            for (int t = 1; t < 512; t += 2)
                if (pidx[t] != 0) { is64 = 0; break; }
            g_idx_is64 = is64;
        }
    }
}

// ---- staging (256 threads, 64 rows x 128 cols k-half) ----
__device__ __forceinline__ void ldg_chunk(
    const float* __restrict__ inputs, const float* __restrict__ ptab,
    const int* __restrict__ sIdxb, int n, int tbase, int half, int nr,
    int sl, int rq, float4* ra, float4* rb)
{
    const int col0 = half * 128 + sl * 4;
    #pragma unroll
    for (int m = 0; m < 8; ++m) {
        const int r = rq + m * 8;
        ra[m] = make_float4(0.f, 0.f, 0.f, 0.f);
        rb[m] = ra[m];
        if (r < nr) {
            ra[m] = *(const float4*)(inputs + (size_t)(n * T_SEQ + tbase + r) * DQ + col0);
            rb[m] = *(const float4*)(ptab + (size_t)sIdxb[r] * DQ + col0);
        }
    }
}

__device__ __forceinline__ void sts_chunk(char* smem, int pbuf, int sl, int rq,
                                          const float4* ra, const float4* rb)
{
    #pragma unroll
    for (int m = 0; m < 8; ++m) {
        const int r = rq + m * 8;
        const float x0 = ra[m].x + rb[m].x, x1 = ra[m].y + rb[m].y;
        const float x2 = ra[m].z + rb[m].z, x3 = ra[m].w + rb[m].w;
        const uint h01 = packbf(x0, x1), h23 = packbf(x2, x3);
        const float2 f01 = bf2f(h01), f23 = bf2f(h23);
        const uint l01 = packbf(x0 - f01.x, x1 - f01.y);
        const uint l23 = packbf(x2 - f23.x, x3 - f23.y);
        *(uint4*)(smem + pbuf * XBYTES + r * 544 + sl * 16) = make_uint4(h01, l01, h23, l23);
    }
}

// =====================================================================
// Main kernel: persistent CTAs; tensor-core logits GEMM AND V GEMM.
// =====================================================================
__global__ void __launch_bounds__(THREADS, 2)
attn_kernel(const float* __restrict__ inputs, const int* __restrict__ pidx,
            const float* __restrict__ ptab, float* __restrict__ out,
            float* __restrict__ scores)
{
    extern __shared__ char smem[];
    char* sLog = smem + OFF_X1;                // aliases X buffer 1
    int*  sIdx = (int*)(smem + OFF_IDX);       // 2 x 64

    const int tid  = threadIdx.x;
    const int lane = tid & 31;
    const int w    = tid >> 5;          // 0..7
    const int rg4  = w & 3;
    const int jt0  = (w >> 2) * 5;      // logits n-split
    const int hg   = w >> 2;            // V-GEMM head group
    const int gr   = lane >> 2, q = lane & 3;
    const int sl   = tid & 31, rq = tid >> 5;
    const int is64 = g_idx_is64;

    // ---- prologue: item0 idx ----
    {
        const int item0 = blockIdx.x;
        if (tid < 64) {
            const int n0 = item0 >> 5, tb0 = (item0 & 31) << 6;
            int v = 0;
            if (tb0 + tid < T_SEQ) {
                const int pos = n0 * T_SEQ + tb0 + tid;
                v = is64 ? pidx[2 * pos] : pidx[pos];
            }
            sIdx[tid] = v;
        }
    }
    __syncthreads();

    // stage item0 chunk half0 -> buf0
    {
        const int item0 = blockIdx.x;
        const int n0 = item0 >> 5, tb0 = (item0 & 31) << 6;
        const int nr0 = min(TILE, T_SEQ - tb0);
        float4 ra[8], rb[8];
        ldg_chunk(inputs, ptab, sIdx, n0, tb0, 0, nr0, sl, rq, ra, rb);
        sts_chunk(smem, 0, sl, rq, ra, rb);
    }
    __syncthreads();

    float acc[5][4];
    #pragma unroll
    for (int j = 0; j < 5; ++j)
        #pragma unroll
        for (int i = 0; i < 4; ++i) acc[j][i] = 0.f;

    int p = 0, ib = 0;
    #pragma unroll 1
    for (int item = blockIdx.x; item < N_ITEMS; item += GRID_X) {
        const int n = item >> 5, tbase = (item & 31) << 6;
        const int nr = min(TILE, T_SEQ - tbase);
        const int nxt = item + GRID_X;
        const int n2 = nxt >> 5, tb2 = (nxt & 31) << 6;

        // ================== chunk half 0 (buf p) ==================
        float4 ra[8], rb[8];
        ldg_chunk(inputs, ptab, sIdx + ib * 64, n, tbase, 1, nr, sl, rq, ra, rb);
        if (nxt < N_ITEMS && tid < 64) {
            int v = 0;
            if (tb2 + tid < T_SEQ) {
                const int pos = n2 * T_SEQ + tb2 + tid;
                v = is64 ? pidx[2 * pos] : pidx[pos];
            }
            sIdx[(ib ^ 1) * 64 + tid] = v;
        }
        {
            const uint2* a0p = (const uint2*)(smem + p * XBYTES) + (rg4 * 16 + gr) * XSTR + q;
            const uint2* a1p = a0p + 8 * XSTR;
            #pragma unroll
            for (int ks = 0; ks < 8; ++ks) {
                const uint2 A0 = a0p[ks * 8];
                const uint2 A2 = a0p[ks * 8 + 4];
                const uint2 A1 = a1p[ks * 8];
                const uint2 A3 = a1p[ks * 8 + 4];
                #pragma unroll
                for (int j = 0; j < 5; ++j) {
                    const uint4 bf = __ldg(&g_Bf[((jt0 + j) * 16 + ks) * 32 + lane]);
                    mma16816(acc[j], A0.x, A1.x, A2.x, A3.x, bf.x, bf.z);
                    mma16816(acc[j], A0.x, A1.x, A2.x, A3.x, bf.y, bf.w);
                    mma16816(acc[j], A0.y, A1.y, A2.y, A3.y, bf.x, bf.z);
                }
            }
        }
        __syncthreads();   // D0
        sts_chunk(smem, p ^ 1, sl, rq, ra, rb);
        __syncthreads();   // G0
        p ^= 1;

        // ================== chunk half 1 (buf p = buf1) ==================
        if (nxt < N_ITEMS) {
            const int nrn = min(TILE, T_SEQ - tb2);
            ldg_chunk(inputs, ptab, sIdx + (ib ^ 1) * 64, n2, tb2, 0, nrn, sl, rq, ra, rb);
        }
        {
            const uint2* a0p = (const uint2*)(smem + p * XBYTES) + (rg4 * 16 + gr) * XSTR + q;
            const uint2* a1p = a0p + 8 * XSTR;
            #pragma unroll
            for (int ks = 0; ks < 8; ++ks) {
                const uint2 A0 = a0p[ks * 8];
                const uint2 A2 = a0p[ks * 8 + 4];
                const uint2 A1 = a1p[ks * 8];
                const uint2 A3 = a1p[ks * 8 + 4];
                #pragma unroll
                for (int j = 0; j < 5; ++j) {
                    const uint4 bf = __ldg(&g_Bf[((jt0 + j) * 16 + 8 + ks) * 32 + lane]);
                    mma16816(acc[j], A0.x, A1.x, A2.x, A3.x, bf.x, bf.z);
                    mma16816(acc[j], A0.x, A1.x, A2.x, A3.x, bf.y, bf.w);
                    mma16816(acc[j], A0.y, A1.y, A2.y, A3.y, bf.x, bf.z);
                }
            }
        }
        __syncthreads();   // D1: buf1 consumed

        // C: logits fragments -> per-(row, head) slots in sLog (aliases buf1)
        {
            const int r0 = rg4 * 16 + gr;
            #pragma unroll
            for (int j = 0; j < 5; ++j) {
                const int c2 = (jt0 + j) * 8 + 2 * q;
                const int h = c2 / 10;
                const int k = c2 - 10 * h;           // even
                char* sl0 = sLog + r0 * 544 + h * 64 + k * 4;
                *(float2*)(sl0)           = make_float2(acc[j][0], acc[j][1]);
                *(float2*)(sl0 + 8 * 544) = make_float2(acc[j][2], acc[j][3]);
                #pragma unroll
                for (int i = 0; i < 4; ++i) acc[j][i] = 0.f;
            }
        }
        if (nxt < N_ITEMS) sts_chunk(smem, p ^ 1, sl, rq, ra, rb);
        __syncthreads();   // frags + sts visible

        // F1: softmax + scores + packed bf16 hi/lo attn (in-slot overwrite)
        {
            const int r = tid & 63;
            const int h0 = tid >> 6;        // 0..3
            #pragma unroll
            for (int hh = 0; hh < 2; ++hh) {
                const int h = h0 + hh * 4;
                char* slot = sLog + r * 544 + h * 64;
                const float4 L0 = *(const float4*)(slot);
                const float4 L1 = *(const float4*)(slot + 16);
                const float2 L2 = *(const float2*)(slot + 32);
                float lg[NTOK] = {L0.x, L0.y, L0.z, L0.w, L1.x, L1.y, L1.z, L1.w, L2.x, L2.y};
                float mx = lg[0];
                #pragma unroll
                for (int k = 1; k < NTOK; ++k) mx = fmaxf(mx, lg[k]);
                float s = 0.f, at[NTOK];
                #pragma unroll
                for (int k = 0; k < NTOK; ++k) { at[k] = __expf(lg[k] - mx); s += at[k]; }
                const float inv = 1.0f / s;
                #pragma unroll
                for (int k = 0; k < NTOK; ++k) at[k] *= inv;
                if (r < nr) {
                    float* sp = scores + ((size_t)n * NJ + h * NTOK) * T_SEQ + tbase + r;
                    #pragma unroll
                    for (int k = 0; k < NTOK; ++k) sp[(size_t)k * T_SEQ] = at[k];
                }
                // pack attn -> bf16 {hi,lo} k-pairs, zero pad k=10..15
                uint hi[5], lo[5];
                #pragma unroll
                for (int kp = 0; kp < 5; ++kp) {
                    hi[kp] = packbf(at[2 * kp], at[2 * kp + 1]);
                    const float2 f = bf2f(hi[kp]);
                    lo[kp] = packbf(at[2 * kp] - f.x, at[2 * kp + 1] - f.y);
                }
                *(uint4*)(slot)      = make_uint4(hi[0], lo[0], hi[1], lo[1]);
                *(uint4*)(slot + 16) = make_uint4(hi[2], lo[2], hi[3], lo[3]);
                *(uint4*)(slot + 32) = make_uint4(hi[4], lo[4], 0u, 0u);
                *(uint4*)(slot + 48) = make_uint4(0u, 0u, 0u, 0u);
            }
        }
        __syncthreads();   // packed attn visible

        // F2: out = attn @ vh on tensor cores (one k16 step per head)
        {
            const int r0 = rg4 * 16;
            const float* outb = out + (size_t)(n * T_SEQ + tbase) * DQ;
            const int r1 = r0 + gr, r2 = r0 + gr + 8;
            #pragma unroll
            for (int hh = 0; hh < 4; ++hh) {
                const int h = hg * 4 + hh;
                const char* arow = sLog + r1 * 544 + h * 64;
                const uint2 A01a = *(const uint2*)(arow + q * 8);          // row r1, k 2q   {hi,lo}
                const uint2 A23a = *(const uint2*)(arow + (q + 4) * 8);    // row r1, k 2q+8
                const uint2 A01b = *(const uint2*)(arow + 8 * 544 + q * 8);
                const uint2 A23b = *(const uint2*)(arow + 8 * 544 + (q + 4) * 8);
                #pragma unroll
                for (int j = 0; j < 4; ++j) {
                    const uint4 bf = __ldg(&g_Vf[h * 128 + j * 32 + lane]);
                    float c4[4] = {0.f, 0.f, 0.f, 0.f};
                    mma16816(c4, A01a.x, A01b.x, A23a.x, A23b.x, bf.x, bf.z);  // hi*hi
                    mma16816(c4, A01a.x, A01b.x, A23a.x, A23b.x, bf.y, bf.w);  // hi*lo
                    mma16816(c4, A01a.y, A01b.y, A23a.y, A23b.y, bf.x, bf.z);  // lo*hi
                    const int col = 32 * h + 8 * j + 2 * q;
                    if (r1 < nr)
                        *(float2*)((float*)outb + (size_t)r1 * DQ + col) = make_float2(c4[0], c4[1]);
                    if (r2 < nr)
                        *(float2*)((float*)outb + (size_t)r2 * DQ + col) = make_float2(c4[2], c4[3]);
                }
            }
        }
        // no trailing sync: next item's D0 covers the sLog hazard
        p ^= 1;
        ib ^= 1;
    }
}

extern "C" void kernel_launch(void* const* d_in, const int* in_sizes, int n_in,
                              void* d_out, int out_size) {
    const float* inputs = (const float*)d_in[0];
    const int*   pidx   = (const int*)d_in[1];
    const float* embed  = (const float*)d_in[2];
    const float* Wq     = (const float*)d_in[3];
    const float* Wk     = (const float*)d_in[4];
    const float* Wv     = (const float*)d_in[5];
    const float* ptab   = (const float*)d_in[6];

    float* out    = (float*)d_out;
    float* scores = (float*)d_out + OUT_ELEMS;

    cudaFuncSetAttribute(attn_kernel, cudaFuncAttributeMaxDynamicSharedMemorySize, SMEM_BYTES);

    precompute_kernel<<<NJ + 1, 256>>>(embed, Wq, Wk, Wv, pidx);
    attn_kernel<<<GRID_X, THREADS, SMEM_BYTES>>>(inputs, pidx, ptab, out, scores);
}